// round 1
// baseline (speedup 1.0000x reference)
#include <cuda_runtime.h>
#include <math.h>

#define TILE 32
#define IMG_H 512
#define IMG_W 512
#define NTHREADS 256

// Global double accumulator for the loss sum (scale-weighted |diff| over all
// pixels, features, windows). Zeroed by init kernel each launch.
__device__ double g_acc;

__global__ void init_acc_kernel() { g_acc = 0.0; }

__global__ void finalize_kernel(float* out, double scale) {
    out[0] = (float)(g_acc * scale);
}

template <int K>
__global__ __launch_bounds__(NTHREADS)
void stat_loss_kernel(const float* __restrict__ pred,
                      const float* __restrict__ tgt)
{
    constexpr int R1  = K / 2;          // conv radius
    constexpr int R2  = 2 * R1;         // double halo (mean needed at halo R1)
    constexpr int MS  = TILE + 2 * R1;  // mean-region side
    constexpr int XS  = TILE + 2 * R2;  // x-region side (rows)
    constexpr int XSC = XS + 4;         // padded cols (blocked overreads)
    constexpr int HBR = XS + 4;         // padded rows for hb (blocked overreads)
    constexpr int NG  = (MS + 3) / 4;   // groups of 4 over MS

    __shared__ float xs[XS][XSC];       // x tile with halo R2
    __shared__ float hb[HBR][MS];       // horizontal-conv scratch
    __shared__ float mb[MS][MS];        // mean field (inner + halo R1)
    __shared__ float c3[MS][MS];        // (x-mean)^3
    __shared__ float c4[MS][MS];        // (x-mean)^4
    __shared__ float wsum[NTHREADS / 32];

    const int tid = threadIdx.x;
    const int x0 = blockIdx.x * TILE;
    const int y0 = blockIdx.y * TILE;
    const size_t plane_off = (size_t)blockIdx.z * (size_t)(IMG_H * IMG_W);

    // normalized 1D gaussian weights (2D window is its outer product)
    float g[K];
    {
        const float sigma = (float)K / 6.0f;
        const float inv2s2 = 1.0f / (2.0f * sigma * sigma);
        float s = 0.0f;
#pragma unroll
        for (int j = 0; j < K; ++j) {
            float c = (float)(j - K / 2);
            g[j] = expf(-c * c * inv2s2);
            s += g[j];
        }
        float inv = 1.0f / s;
#pragma unroll
        for (int j = 0; j < K; ++j) g[j] *= inv;
    }

    // output ownership: thread (tid) -> col (tid&31), rows ory..ory+3
    const int ocx = tid & (TILE - 1);
    const int ory = (tid >> 5) * 4;

    float fm[4], fv[4], fs[4], fk[4];   // pred features (registers)
    float acc = 0.0f;

#pragma unroll 1
    for (int t = 0; t < 2; ++t) {
        const float* src = (t == 0 ? pred : tgt) + plane_off;

        // ---- stage 1: load x tile (halo R2), zero outside image ----
        for (int idx = tid; idx < XS * XS; idx += NTHREADS) {
            int ry = idx / XS, rx = idx - ry * XS;
            int gy = y0 - R2 + ry, gx = x0 - R2 + rx;
            float v = 0.0f;
            if ((unsigned)gy < (unsigned)IMG_H && (unsigned)gx < (unsigned)IMG_W)
                v = src[gy * IMG_W + gx];
            xs[ry][rx] = v;
        }
        __syncthreads();

        // ---- stage 2: horizontal mean conv -> hb[XS][MS] (4-wide blocked) ----
        for (int idx = tid; idx < XS * NG; idx += NTHREADS) {
            int ry = idx / NG;
            int cx = (idx - ry * NG) * 4;
            float v[K + 3];
#pragma unroll
            for (int q = 0; q < K + 3; ++q) v[q] = xs[ry][cx + q];
#pragma unroll
            for (int rr = 0; rr < 4; ++rr) {
                if (cx + rr < MS) {
                    float a = 0.0f;
#pragma unroll
                    for (int j = 0; j < K; ++j) a = fmaf(g[j], v[rr + j], a);
                    hb[ry][cx + rr] = a;
                }
            }
        }
        __syncthreads();

        // ---- stage 3: vertical mean conv -> mb[MS][MS] (4-row blocked) ----
        for (int idx = tid; idx < NG * MS; idx += NTHREADS) {
            int grow = idx / MS, cx = idx - grow * MS;
            int ry = grow * 4;
            float v[K + 3];
#pragma unroll
            for (int q = 0; q < K + 3; ++q) v[q] = hb[ry + q][cx];
#pragma unroll
            for (int rr = 0; rr < 4; ++rr) {
                if (ry + rr < MS) {
                    float a = 0.0f;
#pragma unroll
                    for (int j = 0; j < K; ++j) a = fmaf(g[j], v[rr + j], a);
                    mb[ry + rr][cx] = a;
                }
            }
        }
        __syncthreads();

        // ---- stage 4: centered powers, zero outside image (zero padding) ----
        for (int idx = tid; idx < MS * MS; idx += NTHREADS) {
            int ry = idx / MS, cx = idx - ry * MS;
            int gy = y0 - R1 + ry, gx = x0 - R1 + cx;
            float v3 = 0.0f, v4 = 0.0f;
            if ((unsigned)gy < (unsigned)IMG_H && (unsigned)gx < (unsigned)IMG_W) {
                float xc = xs[ry + R1][cx + R1] - mb[ry][cx];
                float x2 = xc * xc;
                v3 = x2 * xc;
                v4 = x2 * x2;
            }
            c3[ry][cx] = v3;
            c4[ry][cx] = v4;
        }
        __syncthreads();

        // ---- stage 5: horizontal conv of x^2 -> hb[MS][TILE] ----
        for (int idx = tid; idx < MS * (TILE / 4); idx += NTHREADS) {
            int ry = idx / (TILE / 4);
            int cx = (idx - ry * (TILE / 4)) * 4;
            float v[K + 3];
#pragma unroll
            for (int q = 0; q < K + 3; ++q) {
                float x = xs[ry + R1][cx + R1 + q];
                v[q] = x * x;
            }
#pragma unroll
            for (int rr = 0; rr < 4; ++rr) {
                float a = 0.0f;
#pragma unroll
                for (int j = 0; j < K; ++j) a = fmaf(g[j], v[rr + j], a);
                hb[ry][cx + rr] = a;
            }
        }
        __syncthreads();

        // ---- stage 6: vertical conv -> s2; mean & var features ----
        float tm[4], tv[4];
        {
            float v[K + 3];
#pragma unroll
            for (int q = 0; q < K + 3; ++q) v[q] = hb[ory + q][ocx];
#pragma unroll
            for (int rr = 0; rr < 4; ++rr) {
                float a = 0.0f;
#pragma unroll
                for (int j = 0; j < K; ++j) a = fmaf(g[j], v[rr + j], a);
                float m = mb[ory + rr + R1][ocx + R1];
                tm[rr] = m;
                tv[rr] = fmaxf(a - m * m, 1e-8f);
            }
        }
        __syncthreads();

        // ---- stage 7: horizontal conv of xc^3 -> hb[MS][TILE] ----
        for (int idx = tid; idx < MS * (TILE / 4); idx += NTHREADS) {
            int ry = idx / (TILE / 4);
            int cx = (idx - ry * (TILE / 4)) * 4;
            float v[K + 3];
#pragma unroll
            for (int q = 0; q < K + 3; ++q) v[q] = c3[ry][cx + q];
#pragma unroll
            for (int rr = 0; rr < 4; ++rr) {
                float a = 0.0f;
#pragma unroll
                for (int j = 0; j < K; ++j) a = fmaf(g[j], v[rr + j], a);
                hb[ry][cx + rr] = a;
            }
        }
        __syncthreads();

        // ---- stage 8: vertical conv -> m3; skew feature ----
        float ts[4];
        {
            float v[K + 3];
#pragma unroll
            for (int q = 0; q < K + 3; ++q) v[q] = hb[ory + q][ocx];
#pragma unroll
            for (int rr = 0; rr < 4; ++rr) {
                float a = 0.0f;
#pragma unroll
                for (int j = 0; j < K; ++j) a = fmaf(g[j], v[rr + j], a);
                float sd = sqrtf(tv[rr]);
                ts[rr] = a / (sd * sd * sd + 1e-8f);
            }
        }
        __syncthreads();

        // ---- stage 9: horizontal conv of xc^4 -> hb[MS][TILE] ----
        for (int idx = tid; idx < MS * (TILE / 4); idx += NTHREADS) {
            int ry = idx / (TILE / 4);
            int cx = (idx - ry * (TILE / 4)) * 4;
            float v[K + 3];
#pragma unroll
            for (int q = 0; q < K + 3; ++q) v[q] = c4[ry][cx + q];
#pragma unroll
            for (int rr = 0; rr < 4; ++rr) {
                float a = 0.0f;
#pragma unroll
                for (int j = 0; j < K; ++j) a = fmaf(g[j], v[rr + j], a);
                hb[ry][cx + rr] = a;
            }
        }
        __syncthreads();

        // ---- stage 10: vertical conv -> m4; kurtosis feature ----
        float tk[4];
        {
            float v[K + 3];
#pragma unroll
            for (int q = 0; q < K + 3; ++q) v[q] = hb[ory + q][ocx];
#pragma unroll
            for (int rr = 0; rr < 4; ++rr) {
                float a = 0.0f;
#pragma unroll
                for (int j = 0; j < K; ++j) a = fmaf(g[j], v[rr + j], a);
                tk[rr] = a / (tv[rr] * tv[rr] + 1e-8f);
            }
        }

        if (t == 0) {
#pragma unroll
            for (int rr = 0; rr < 4; ++rr) {
                fm[rr] = tm[rr]; fv[rr] = tv[rr];
                fs[rr] = ts[rr]; fk[rr] = tk[rr];
            }
        } else {
#pragma unroll
            for (int rr = 0; rr < 4; ++rr) {
                acc += fabsf(fm[rr] - tm[rr])
                     + fabsf(fv[rr] - tv[rr])
                     + 0.5f   * fabsf(fs[rr] - ts[rr])
                     + 0.001f * fabsf(fk[rr] - tk[rr]);
            }
        }
        __syncthreads();
    }

    // ---- block reduction, atomic accumulate ----
#pragma unroll
    for (int off = 16; off > 0; off >>= 1)
        acc += __shfl_xor_sync(0xffffffffu, acc, off);
    if ((tid & 31) == 0) wsum[tid >> 5] = acc;
    __syncthreads();
    if (tid < 32) {
        float v = (tid < NTHREADS / 32) ? wsum[tid] : 0.0f;
#pragma unroll
        for (int off = 16; off > 0; off >>= 1)
            v += __shfl_xor_sync(0xffffffffu, v, off);
        if (tid == 0) atomicAdd(&g_acc, (double)v);
    }
}

extern "C" void kernel_launch(void* const* d_in, const int* in_sizes, int n_in,
                              void* d_out, int out_size) {
    const float* pred = (const float*)d_in[0];
    const float* tgt  = (const float*)d_in[1];
    float* out = (float*)d_out;

    const int npix = in_sizes[0];                     // 16*3*512*512
    const int planes = npix / (IMG_H * IMG_W);        // 48

    dim3 grid(IMG_W / TILE, IMG_H / TILE, planes);

    init_acc_kernel<<<1, 1>>>();
    stat_loss_kernel<3><<<grid, NTHREADS>>>(pred, tgt);
    stat_loss_kernel<5><<<grid, NTHREADS>>>(pred, tgt);
    stat_loss_kernel<7><<<grid, NTHREADS>>>(pred, tgt);

    // total / num_features, mean over npix elements per feature
    const double scale = 1.0 / (12.0 * (double)npix);
    finalize_kernel<<<1, 1>>>(out, scale);
}

// round 3
// speedup vs baseline: 1.0654x; 1.0654x over previous
#include <cuda_runtime.h>
#include <math.h>

#define TILE 32
#define IMG_H 512
#define IMG_W 512
#define NTHREADS 256

typedef unsigned long long ull;

__device__ double g_acc;

__global__ void init_acc_kernel() { g_acc = 0.0; }

__global__ void finalize_kernel(float* out, double scale) {
    out[0] = (float)(g_acc * scale);
}

// ---- f32x2 packed helpers ----
__device__ __forceinline__ ull pack2(float lo, float hi) {
    ull r;
    asm("mov.b64 %0, {%1, %2};" : "=l"(r) : "f"(lo), "f"(hi));
    return r;
}
__device__ __forceinline__ void unpack2(ull v, float& lo, float& hi) {
    asm("mov.b64 {%0, %1}, %2;" : "=f"(lo), "=f"(hi) : "l"(v));
}
__device__ __forceinline__ void ffma2(ull& d, ull a, ull b) {
    asm("fma.rn.f32x2 %0, %1, %2, %0;" : "+l"(d) : "l"(a), "l"(b));
}

template <int K>
__global__ __launch_bounds__(NTHREADS)
void stat_loss_kernel(const float* __restrict__ pred,
                      const float* __restrict__ tgt)
{
    constexpr int R   = K / 2;
    constexpr int XS  = TILE + 4 * R;   // x tile side (double halo)
    constexpr int MS  = TILE + 2 * R;   // mean-field side (single halo)
    constexpr int XSP = 49;             // xs row stride (floats, odd)
    constexpr int HBW = 41;             // hb row stride (u64, odd)
    constexpr int HBR = 48;             // hb rows (padded for 8-row tail)
    constexpr int MBW = 41;             // mb row stride (u64)
    constexpr int MBR = 40;             // mb rows (padded)
    constexpr int F2W = 47;             // f2 row stride (u64)
    constexpr int H2W = 33;             // h2 row stride (u64, odd)
    constexpr int QH  = 8 + K - 1;      // taps per 8-wide horizontal group
    constexpr int QV8 = 8 + K - 1;      // taps per 8-row vertical group
    constexpr int QV4 = 4 + K - 1;      // taps per 4-row vertical group

    // buffer sizes (bytes)
    constexpr int XS_B = XS * XSP * 4;          // x tile
    constexpr int H2_B = MS * H2W * 8;          // level-2 horiz out
    constexpr int HB_B = HBR * HBW * 8;         // level-1 horiz out
    constexpr int F2_B = MS * F2W * 8;          // (xc^3, xc^4) field
    constexpr int A_B  = (XS_B > H2_B ? XS_B : H2_B);   // xs ∪ h2
    constexpr int B_B  = (HB_B > F2_B ? HB_B : F2_B);   // hb ∪ f2
    constexpr int MB_B = MBR * MBW * 8;

    __shared__ __align__(16) unsigned char smem[A_B + B_B + MB_B];
    __shared__ float wsum[NTHREADS / 32];

    float* xs = (float*)smem;               // stage 1-3.5
    ull*   h2 = (ull*)smem;                 // stage 4-5 (aliases xs)
    ull*   hb = (ull*)(smem + A_B);         // stage 2-3
    ull*   f2 = (ull*)(smem + A_B);         // stage 3.5-4 (aliases hb)
    ull*   mb = (ull*)(smem + A_B + B_B);   // (mean, S2) field

    const int tid = threadIdx.x;
    const int x0 = blockIdx.x * TILE;
    const int y0 = blockIdx.y * TILE;
    const size_t plane_off = (size_t)blockIdx.z * (size_t)(IMG_H * IMG_W);

    // normalized 1D gaussian
    float g[K];
    ull gp[K];
    {
        const float sigma = (float)K / 6.0f;
        const float inv2s2 = 1.0f / (2.0f * sigma * sigma);
        float s = 0.0f;
#pragma unroll
        for (int j = 0; j < K; ++j) {
            float c = (float)(j - K / 2);
            g[j] = expf(-c * c * inv2s2);
            s += g[j];
        }
        float inv = 1.0f / s;
#pragma unroll
        for (int j = 0; j < K; ++j) { g[j] *= inv; gp[j] = pack2(g[j], g[j]); }
    }

    const bool edge = (x0 < 2 * R) || (y0 < 2 * R) ||
                      (x0 + TILE + 2 * R > IMG_W) || (y0 + TILE + 2 * R > IMG_H);

    // stage mappings (compile-time group layouts, single shot)
    const int s2_row = tid / 5, s2_cx = (tid % 5) * 8;        // XS rows × 5 grp
    const int s3_c = tid % MS, s3_r0 = (tid / MS) * 8;        // MS cols × 5 grp
    const int s4_row = tid >> 2, s4_cx = (tid & 3) * 8;       // MS rows × 4 grp
    const int ocx = tid & 31, org = (tid >> 5) * 4;           // 32 cols × 8 grp

    float fm[4], fv[4], fs[4], fk[4];
    float acc = 0.0f;

#pragma unroll 1
    for (int t = 0; t < 2; ++t) {
        const float* src = (t == 0 ? pred : tgt) + plane_off;

        // ---- S1: load x tile (halo 2R) ----
        if (!edge) {
            const float* base = src + (size_t)(y0 - 2 * R) * IMG_W + (x0 - 2 * R);
            for (int idx = tid; idx < XS * XS; idx += NTHREADS) {
                int ry = idx / XS, rx = idx - ry * XS;
                xs[ry * XSP + rx] = base[ry * IMG_W + rx];
            }
        } else {
            for (int idx = tid; idx < XS * XS; idx += NTHREADS) {
                int ry = idx / XS, rx = idx - ry * XS;
                int gy = y0 - 2 * R + ry, gx = x0 - 2 * R + rx;
                float v = 0.0f;
                if ((unsigned)gy < (unsigned)IMG_H && (unsigned)gx < (unsigned)IMG_W)
                    v = src[gy * IMG_W + gx];
                xs[ry * XSP + rx] = v;
            }
        }
        __syncthreads();

        // ---- S2: horizontal conv of (x, x^2), 8-wide, packed ----
        if (tid < XS * 5) {
            const float* xrow = xs + s2_row * XSP + s2_cx;
            ull a[8];
#pragma unroll
            for (int rr = 0; rr < 8; ++rr) a[rr] = 0ull;
#pragma unroll
            for (int q = 0; q < QH; ++q) {
                float x = xrow[q];
                ull p = pack2(x, x * x);
#pragma unroll
                for (int rr = 0; rr < 8; ++rr) {
                    int j = q - rr;
                    if (j >= 0 && j < K) ffma2(a[rr], gp[j], p);
                }
            }
            ull* hrow = hb + s2_row * HBW + s2_cx;
#pragma unroll
            for (int rr = 0; rr < 8; ++rr) hrow[rr] = a[rr];
        }
        __syncthreads();

        // ---- S3: vertical conv -> mb = (mean, S2), 8-row, packed ----
        if (tid < MS * 5) {
            const ull* hcol = hb + s3_r0 * HBW + s3_c;
            ull a[8];
#pragma unroll
            for (int rr = 0; rr < 8; ++rr) a[rr] = 0ull;
#pragma unroll
            for (int q = 0; q < QV8; ++q) {
                ull p = hcol[q * HBW];
#pragma unroll
                for (int rr = 0; rr < 8; ++rr) {
                    int j = q - rr;
                    if (j >= 0 && j < K) ffma2(a[rr], gp[j], p);
                }
            }
            ull* mcol = mb + s3_r0 * MBW + s3_c;
#pragma unroll
            for (int rr = 0; rr < 8; ++rr) mcol[rr * MBW] = a[rr];
        }
        __syncthreads();

        // ---- S3.5: centered power field f2 = (xc^3, xc^4), zero outside ----
        if (!edge) {
            for (int idx = tid; idx < MS * MS; idx += NTHREADS) {
                int ry = idx / MS, cx = idx - ry * MS;
                float x = xs[(ry + R) * XSP + (cx + R)];
                float mean, s2v;
                unpack2(mb[ry * MBW + cx], mean, s2v);
                float xc = x - mean;
                float xc2 = xc * xc;
                f2[ry * F2W + cx] = pack2(xc2 * xc, xc2 * xc2);
            }
        } else {
            for (int idx = tid; idx < MS * MS; idx += NTHREADS) {
                int ry = idx / MS, cx = idx - ry * MS;
                int gy = y0 - R + ry, gx = x0 - R + cx;
                ull v = 0ull;
                if ((unsigned)gy < (unsigned)IMG_H && (unsigned)gx < (unsigned)IMG_W) {
                    float x = xs[(ry + R) * XSP + (cx + R)];
                    float mean, s2v;
                    unpack2(mb[ry * MBW + cx], mean, s2v);
                    float xc = x - mean;
                    float xc2 = xc * xc;
                    v = pack2(xc2 * xc, xc2 * xc2);
                }
                f2[ry * F2W + cx] = v;
            }
        }
        __syncthreads();

        // ---- S4: horizontal conv of (xc^3, xc^4), 8-wide, packed ----
        if (tid < MS * 4) {
            const ull* frow = f2 + s4_row * F2W + s4_cx;
            ull a[8];
#pragma unroll
            for (int rr = 0; rr < 8; ++rr) a[rr] = 0ull;
#pragma unroll
            for (int q = 0; q < QH; ++q) {
                ull p = frow[q];
#pragma unroll
                for (int rr = 0; rr < 8; ++rr) {
                    int j = q - rr;
                    if (j >= 0 && j < K) ffma2(a[rr], gp[j], p);
                }
            }
            ull* orow = h2 + s4_row * H2W + s4_cx;
#pragma unroll
            for (int rr = 0; rr < 8; ++rr) orow[rr] = a[rr];
        }
        __syncthreads();

        // ---- S5: vertical conv -> (m3, m4); features + loss ----
        {
            const ull* hcol = h2 + org * H2W + ocx;
            ull a[4];
#pragma unroll
            for (int rr = 0; rr < 4; ++rr) a[rr] = 0ull;
#pragma unroll
            for (int q = 0; q < QV4; ++q) {
                ull p = hcol[q * H2W];
#pragma unroll
                for (int rr = 0; rr < 4; ++rr) {
                    int j = q - rr;
                    if (j >= 0 && j < K) ffma2(a[rr], gp[j], p);
                }
            }
#pragma unroll
            for (int rr = 0; rr < 4; ++rr) {
                float m3, m4;
                unpack2(a[rr], m3, m4);
                float mean, s2v;
                unpack2(mb[(org + rr + R) * MBW + (ocx + R)], mean, s2v);
                float var = fmaxf(s2v - mean * mean, 1e-8f);
                float sd = sqrtf(var);
                float skew = m3 / (sd * sd * sd + 1e-8f);
                float kurt = m4 / (var * var + 1e-8f);
                if (t == 0) {
                    fm[rr] = mean; fv[rr] = var; fs[rr] = skew; fk[rr] = kurt;
                } else {
                    acc += fabsf(fm[rr] - mean)
                         + fabsf(fv[rr] - var)
                         + 0.5f   * fabsf(fs[rr] - skew)
                         + 0.001f * fabsf(fk[rr] - kurt);
                }
            }
        }
        __syncthreads();   // protect aliased buffers before next tensor
    }

    // ---- block reduction, atomic accumulate ----
#pragma unroll
    for (int off = 16; off > 0; off >>= 1)
        acc += __shfl_xor_sync(0xffffffffu, acc, off);
    if ((tid & 31) == 0) wsum[tid >> 5] = acc;
    __syncthreads();
    if (tid < 32) {
        float v = (tid < NTHREADS / 32) ? wsum[tid] : 0.0f;
#pragma unroll
        for (int off = 16; off > 0; off >>= 1)
            v += __shfl_xor_sync(0xffffffffu, v, off);
        if (tid == 0) atomicAdd(&g_acc, (double)v);
    }
}

extern "C" void kernel_launch(void* const* d_in, const int* in_sizes, int n_in,
                              void* d_out, int out_size) {
    const float* pred = (const float*)d_in[0];
    const float* tgt  = (const float*)d_in[1];
    float* out = (float*)d_out;

    const int npix = in_sizes[0];                 // 16*3*512*512
    const int planes = npix / (IMG_H * IMG_W);    // 48

    dim3 grid(IMG_W / TILE, IMG_H / TILE, planes);

    init_acc_kernel<<<1, 1>>>();
    stat_loss_kernel<3><<<grid, NTHREADS>>>(pred, tgt);
    stat_loss_kernel<5><<<grid, NTHREADS>>>(pred, tgt);
    stat_loss_kernel<7><<<grid, NTHREADS>>>(pred, tgt);

    const double scale = 1.0 / (12.0 * (double)npix);
    finalize_kernel<<<1, 1>>>(out, scale);
}

// round 4
// speedup vs baseline: 1.1422x; 1.0720x over previous
#include <cuda_runtime.h>
#include <math.h>

#define TILE 32
#define IMG_H 512
#define IMG_W 512
#define NTHREADS 256

typedef unsigned long long ull;

__device__ double g_acc;

__global__ void init_acc_kernel() { g_acc = 0.0; }

__global__ void finalize_kernel(float* out, double scale) {
    out[0] = (float)(g_acc * scale);
}

// ---- f32x2 packed helpers ----
__device__ __forceinline__ ull pack2(float lo, float hi) {
    ull r;
    asm("mov.b64 %0, {%1, %2};" : "=l"(r) : "f"(lo), "f"(hi));
    return r;
}
__device__ __forceinline__ void unpack2(ull v, float& lo, float& hi) {
    asm("mov.b64 {%0, %1}, %2;" : "=f"(lo), "=f"(hi) : "l"(v));
}
__device__ __forceinline__ void ffma2(ull& d, ull a, ull b) {
    asm("fma.rn.f32x2 %0, %1, %2, %0;" : "+l"(d) : "l"(a), "l"(b));
}

template <int K>
__global__ __launch_bounds__(NTHREADS)
void stat_loss_kernel(const float* __restrict__ pred,
                      const float* __restrict__ tgt)
{
    constexpr int R   = K / 2;
    constexpr int XS  = TILE + 4 * R;   // x tile side (double halo)
    constexpr int MS  = TILE + 2 * R;   // mean-field side (single halo)
    constexpr int XSP = 47;             // xs row stride (floats, odd)
    constexpr int HBW = 41;             // hb row stride (u64, odd)
    constexpr int HBR = 48;             // hb allocated rows
    constexpr int MSW = 39;             // ms/vs row stride (floats, odd)
    constexpr int MSR = 40;             // ms/vs allocated rows
    constexpr int H2W = 33;             // h2 row stride (u64, odd)
    constexpr int QH  = 8 + K - 1;      // taps per 8-wide horizontal group
    constexpr int QV8 = 8 + K - 1;      // taps per 8-row vertical group
    constexpr int QV4 = 4 + K - 1;      // taps per 4-row vertical group

    constexpr int XS_B = ((XS * XSP * 4 + 15) / 16) * 16;   // xs bytes
    constexpr int HB_B = HBR * HBW * 8;                     // hb bytes
    constexpr int H2_B = MS * H2W * 8;                      // h2 bytes
    constexpr int B_B  = (HB_B > H2_B ? HB_B : H2_B);       // hb ∪ h2
    constexpr int MS_B = MSR * MSW * 4;

    __shared__ __align__(16) unsigned char smem[XS_B + B_B + 2 * MS_B];
    __shared__ float wsum[NTHREADS / 32];

    float* xs = (float*)smem;                    // x tile (live S1..S4)
    ull*   hb = (ull*)(smem + XS_B);             // level-1 horiz out (S2..S3)
    ull*   h2 = (ull*)(smem + XS_B);             // level-2 horiz out (S4..S5), aliases hb
    float* ms = (float*)(smem + XS_B + B_B);     // mean field
    float* vs = (float*)(smem + XS_B + B_B + MS_B); // variance field

    const int tid = threadIdx.x;
    const int x0 = blockIdx.x * TILE;
    const int y0 = blockIdx.y * TILE;
    const size_t plane_off = (size_t)blockIdx.z * (size_t)(IMG_H * IMG_W);

    // normalized 1D gaussian
    float g[K];
    ull gp[K];
    {
        const float sigma = (float)K / 6.0f;
        const float inv2s2 = 1.0f / (2.0f * sigma * sigma);
        float s = 0.0f;
#pragma unroll
        for (int j = 0; j < K; ++j) {
            float c = (float)(j - K / 2);
            g[j] = expf(-c * c * inv2s2);
            s += g[j];
        }
        float inv = 1.0f / s;
#pragma unroll
        for (int j = 0; j < K; ++j) { g[j] *= inv; gp[j] = pack2(g[j], g[j]); }
    }

    const bool edge = (x0 < 2 * R) || (y0 < 2 * R) ||
                      (x0 + TILE + 2 * R > IMG_W) || (y0 + TILE + 2 * R > IMG_H);

    // stage mappings (single shot)
    const int s2_row = tid / 5, s2_cx = (tid % 5) * 8;    // XS rows × 5 groups
    const int s3_c = tid % MS, s3_r0 = (tid / MS) * 8;    // MS cols × 5 groups
    const int s4_row = tid >> 2, s4_cx = (tid & 3) * 8;   // MS rows × 4 groups
    const int ocx = tid & 31, org = (tid >> 5) * 4;       // 32 cols × 8 groups

    float fm[4], fv[4], fs[4], fk[4];
    float acc = 0.0f;

#pragma unroll 1
    for (int t = 0; t < 2; ++t) {
        const float* src = (t == 0 ? pred : tgt) + plane_off;

        // ---- S1: load x tile (halo 2R), zero outside image ----
        if (!edge) {
            const float* base = src + (size_t)(y0 - 2 * R) * IMG_W + (x0 - 2 * R);
            for (int idx = tid; idx < XS * XS; idx += NTHREADS) {
                int ry = idx / XS, rx = idx - ry * XS;
                xs[ry * XSP + rx] = base[ry * IMG_W + rx];
            }
        } else {
            for (int idx = tid; idx < XS * XS; idx += NTHREADS) {
                int ry = idx / XS, rx = idx - ry * XS;
                int gy = y0 - 2 * R + ry, gx = x0 - 2 * R + rx;
                float v = 0.0f;
                if ((unsigned)gy < (unsigned)IMG_H && (unsigned)gx < (unsigned)IMG_W)
                    v = src[gy * IMG_W + gx];
                xs[ry * XSP + rx] = v;
            }
        }
        __syncthreads();

        // ---- S2: horizontal conv of (x, x^2), 8-wide, packed ----
        if (tid < XS * 5) {
            const float* xrow = xs + s2_row * XSP + s2_cx;
            ull a[8];
#pragma unroll
            for (int rr = 0; rr < 8; ++rr) a[rr] = 0ull;
#pragma unroll
            for (int q = 0; q < QH; ++q) {
                float x = xrow[q];
                ull p = pack2(x, x * x);
#pragma unroll
                for (int rr = 0; rr < 8; ++rr) {
                    int j = q - rr;
                    if (j >= 0 && j < K) ffma2(a[rr], gp[j], p);
                }
            }
            ull* hrow = hb + s2_row * HBW + s2_cx;
#pragma unroll
            for (int rr = 0; rr < 8; ++rr)
                if (s2_cx + rr < MS) hrow[rr] = a[rr];
        }
        __syncthreads();

        // ---- S3: vertical conv -> mean field + clipped variance field ----
        if (tid < MS * 5) {
            const ull* hcol = hb + s3_r0 * HBW + s3_c;
            ull a[8];
#pragma unroll
            for (int rr = 0; rr < 8; ++rr) a[rr] = 0ull;
#pragma unroll
            for (int q = 0; q < QV8; ++q) {
                ull p = hcol[q * HBW];
#pragma unroll
                for (int rr = 0; rr < 8; ++rr) {
                    int j = q - rr;
                    if (j >= 0 && j < K) ffma2(a[rr], gp[j], p);
                }
            }
#pragma unroll
            for (int rr = 0; rr < 8; ++rr) {
                if (s3_r0 + rr < MS) {
                    float mean, s2v;
                    unpack2(a[rr], mean, s2v);
                    int o = (s3_r0 + rr) * MSW + s3_c;
                    ms[o] = mean;
                    vs[o] = fmaxf(s2v - mean * mean, 1e-8f);
                }
            }
        }
        __syncthreads();

        // ---- S4 (fused): horizontal conv of (xc^3, xc^4) computed on the fly ----
        if (tid < MS * 4) {
            const float* xrow = xs + (s4_row + R) * XSP + (s4_cx + R);
            const float* mrow = ms + s4_row * MSW + s4_cx;
            ull a[8];
#pragma unroll
            for (int rr = 0; rr < 8; ++rr) a[rr] = 0ull;
            if (!edge) {
#pragma unroll
                for (int q = 0; q < QH; ++q) {
                    float xc = xrow[q] - mrow[q];
                    float xc2 = xc * xc;
                    ull p = pack2(xc2 * xc, xc2 * xc2);
#pragma unroll
                    for (int rr = 0; rr < 8; ++rr) {
                        int j = q - rr;
                        if (j >= 0 && j < K) ffma2(a[rr], gp[j], p);
                    }
                }
            } else {
                const int gy = y0 - R + s4_row;
                const bool rowin = (unsigned)gy < (unsigned)IMG_H;
#pragma unroll
                for (int q = 0; q < QH; ++q) {
                    int gx = x0 - R + s4_cx + q;
                    bool in = rowin && ((unsigned)gx < (unsigned)IMG_W);
                    float xc = xrow[q] - mrow[q];
                    float xc2 = xc * xc;
                    ull p = in ? pack2(xc2 * xc, xc2 * xc2) : 0ull;
#pragma unroll
                    for (int rr = 0; rr < 8; ++rr) {
                        int j = q - rr;
                        if (j >= 0 && j < K) ffma2(a[rr], gp[j], p);
                    }
                }
            }
            ull* orow = h2 + s4_row * H2W + s4_cx;
#pragma unroll
            for (int rr = 0; rr < 8; ++rr) orow[rr] = a[rr];
        }
        __syncthreads();

        // ---- S5: vertical conv -> (m3, m4); features + loss ----
        {
            const ull* hcol = h2 + org * H2W + ocx;
            ull a[4];
#pragma unroll
            for (int rr = 0; rr < 4; ++rr) a[rr] = 0ull;
#pragma unroll
            for (int q = 0; q < QV4; ++q) {
                ull p = hcol[q * H2W];
#pragma unroll
                for (int rr = 0; rr < 4; ++rr) {
                    int j = q - rr;
                    if (j >= 0 && j < K) ffma2(a[rr], gp[j], p);
                }
            }
#pragma unroll
            for (int rr = 0; rr < 4; ++rr) {
                float m3, m4;
                unpack2(a[rr], m3, m4);
                int o = (org + rr + R) * MSW + (ocx + R);
                float mean = ms[o];
                float var  = vs[o];
                float sd = sqrtf(var);
                float skew = m3 / (sd * sd * sd + 1e-8f);
                float kurt = m4 / (var * var + 1e-8f);
                if (t == 0) {
                    fm[rr] = mean; fv[rr] = var; fs[rr] = skew; fk[rr] = kurt;
                } else {
                    acc += fabsf(fm[rr] - mean)
                         + fabsf(fv[rr] - var)
                         + 0.5f   * fabsf(fs[rr] - skew)
                         + 0.001f * fabsf(fk[rr] - kurt);
                }
            }
        }
        __syncthreads();   // protect aliased buffers before next tensor
    }

    // ---- block reduction, atomic accumulate ----
#pragma unroll
    for (int off = 16; off > 0; off >>= 1)
        acc += __shfl_xor_sync(0xffffffffu, acc, off);
    if ((tid & 31) == 0) wsum[tid >> 5] = acc;
    __syncthreads();
    if (tid < 32) {
        float v = (tid < NTHREADS / 32) ? wsum[tid] : 0.0f;
#pragma unroll
        for (int off = 16; off > 0; off >>= 1)
            v += __shfl_xor_sync(0xffffffffu, v, off);
        if (tid == 0) atomicAdd(&g_acc, (double)v);
    }
}

extern "C" void kernel_launch(void* const* d_in, const int* in_sizes, int n_in,
                              void* d_out, int out_size) {
    const float* pred = (const float*)d_in[0];
    const float* tgt  = (const float*)d_in[1];
    float* out = (float*)d_out;

    const int npix = in_sizes[0];                 // 16*3*512*512
    const int planes = npix / (IMG_H * IMG_W);    // 48

    dim3 grid(IMG_W / TILE, IMG_H / TILE, planes);

    init_acc_kernel<<<1, 1>>>();
    stat_loss_kernel<3><<<grid, NTHREADS>>>(pred, tgt);
    stat_loss_kernel<5><<<grid, NTHREADS>>>(pred, tgt);
    stat_loss_kernel<7><<<grid, NTHREADS>>>(pred, tgt);

    const double scale = 1.0 / (12.0 * (double)npix);
    finalize_kernel<<<1, 1>>>(out, scale);
}